// round 2
// baseline (speedup 1.0000x reference)
#include <cuda_runtime.h>
#include <math.h>

// NUFFT layer, analytic band-limited reformulation. All fp32 (Dekker splits
// replace every double from round-1). See round-1 header for the math.
//
//  A_b[m] = sum_p cos(2*pi*m*x_p),  B_b[m] = sum_p sin(2*pi*m*x_p),  m = 0..111
//  field[b,c,n] = sum_m V_c[m] * (A_b[m] cos(2*pi*m*n/N) + B_b[m] sin(2*pi*m*n/N))
//  out[b,p,c]   = (1/N) * sum_{|j|<=7} exp(-(x_p - X_m)^2/(4 tau)) * field[b,c,m0+j]

#define NMESHC 2001
#define NMODES 112          // modes >= 106 underflow to exactly 0 (as in reference fp32)
#define NBATCH 8
#define NPART  1024
#define NPG    8            // particle groups (blocks) per batch in k_modes

__device__ float g_part[NBATCH][NPG][2 * NMODES];   // warp-reduced partial A|B sums
__device__ float g_f[NBATCH][2][NMESHC];            // physical-space field

#define TWO_PI_F 6.2831853071795864769f

// frac(m*x) in ~[-0.5, 0.5] with |err| ~ 2^-25 ; exact for m < 2^7, x fp32.
__device__ __forceinline__ float frac_mx(float m, float x)
{
    float hi = m * x;
    float lo = fmaf(m, x, -hi);           // exact residual (31-bit product)
    return (hi - rintf(hi)) + lo;         // hi - rintf(hi) is exact
}

// ---------------------------------------------------------------------------
// K1: per-mode cos/sin particle sums, chunked rotation recurrence.
// Block = (particle-group pg, batch b), 128 threads = 128 particles.
// Per particle: 7 sincos pairs total (1 step + 6 chunk bases) instead of 112.
// ---------------------------------------------------------------------------
__global__ __launch_bounds__(128) void k_modes(const float* __restrict__ x)
{
    const int pg   = blockIdx.x;
    const int b    = blockIdx.y;
    const int t    = threadIdx.x;
    const int lane = t & 31;
    const int w    = t >> 5;

    const float xv = x[b * NPART + pg * 128 + t];

    __shared__ float sh[4][2 * NMODES];

    float sw_, cw_;                                   // step e^{2*pi*i*x}
    __sincosf(TWO_PI_F * (xv - rintf(xv)), &sw_, &cw_);

#pragma unroll
    for (int c = 0; c < 7; ++c) {                     // 7 chunks x 16 modes
        float zr, zi;
        if (c == 0) { zr = 1.f; zi = 0.f; }
        else {
            float f = frac_mx((float)(16 * c), xv);
            __sincosf(TWO_PI_F * f, &zi, &zr);
        }
#pragma unroll
        for (int j = 0; j < 16; ++j) {
            float a  = zr, bb = zi;                   // this lane's cos/sin for mode m
#pragma unroll
            for (int o = 16; o; o >>= 1) {
                a  += __shfl_down_sync(0xffffffffu, a,  o);
                bb += __shfl_down_sync(0xffffffffu, bb, o);
            }
            if (lane == 0) {
                sh[w][16 * c + j]          = a;
                sh[w][NMODES + 16 * c + j] = bb;
            }
            float nzr = fmaf(zr, cw_, -zi * sw_);     // rotate to next mode
            float nzi = fmaf(zi, cw_,  zr * sw_);
            zr = nzr; zi = nzi;
        }
    }
    __syncthreads();
    for (int m = t; m < 2 * NMODES; m += 128)
        g_part[b][pg][m] = sh[0][m] + sh[1][m] + sh[2][m] + sh[3][m];
}

// ---------------------------------------------------------------------------
// K2: field at all 2001 grid points, both channels.
// 4 independent 28-step rotation chains (ILP=4, exact per-chunk base phases).
// ---------------------------------------------------------------------------
__global__ __launch_bounds__(128) void k_field(
    const float* __restrict__ sigma_var,
    const float* __restrict__ shift0,
    const float* __restrict__ shift1,
    const float* __restrict__ amp0,
    const float* __restrict__ amp1)
{
    const int b = blockIdx.y;
    const int t = threadIdx.x;
    const int n = blockIdx.x * 128 + t;

    __shared__ float sA[NMODES], sB[NMODES], sV0[NMODES], sV1[NMODES];

    const double TWO_PI_D = 6.283185307179586476925286766559;
    const double taud     = 12.0 / ((TWO_PI_D * 2001.0) * (TWO_PI_D * 2001.0));
    const float  TAUF     = (float)taud;
    const float  SQPIOTAU = (float)sqrt(3.14159265358979323846 / taud);

    const float s    = sigma_var[0];
    const float q0   = 25.f * shift0[0] * shift0[0];
    const float q1   = 25.f * shift1[0] * shift1[0];
    const float a0   = amp0[0];
    const float a1   = amp1[0];
    const float FOURPI = 12.566370614359172f;
    const float coef = TAUF - 0.5f * s * s;           // exp(K^2 tau) * exp(-K^2 s^2/2)

    for (int m = t; m < NMODES; m += 128) {
        float a = 0.f, bb = 0.f;
#pragma unroll
        for (int pg = 0; pg < NPG; ++pg) {
            a  += g_part[b][pg][m];
            bb += g_part[b][pg][NMODES + m];
        }
        sA[m] = a; sB[m] = bb;
        float kk = TWO_PI_F * (float)m;
        float K2 = kk * kk;
        float e  = SQPIOTAU * __expf(coef * K2);      // 0 for m >= 106 (as reference)
        float fold = (m == 0) ? 1.f : 2.f;
        sV0[m] = fold * (-a0) * FOURPI / (K2 + q0) * e;
        float inv = 1.f / (K2 + q1);
        sV1[m] = fold * a1 * FOURPI * inv * inv * e;
    }
    __syncthreads();
    if (n >= NMESHC) return;

    // phi = n/2001, Dekker-accurate (fp32 pair, ~2^-45)
    const float C_HI = (float)(1.0 / 2001.0);
    const float C_LO = (float)(1.0 / 2001.0 - (double)((float)(1.0 / 2001.0)));
    const float nf     = (float)n;
    const float phi_hi = nf * C_HI;
    const float phi_lo = fmaf(nf, C_HI, -phi_hi) + nf * C_LO;

    float sw_, cw_;                                   // step e^{2*pi*i*phi}
    __sincosf(TWO_PI_F * ((phi_hi - rintf(phi_hi)) + phi_lo), &sw_, &cw_);

    float zr[4], zi[4];
    zr[0] = 1.f; zi[0] = 0.f;
#pragma unroll
    for (int c = 1; c < 4; ++c) {                     // base phase at m0 = 28c, exact
        float m0f = (float)(28 * c);
        float hi2 = m0f * phi_hi;
        float lo2 = fmaf(m0f, phi_hi, -hi2);
        float f   = (hi2 - rintf(hi2)) + (lo2 + m0f * phi_lo);
        __sincosf(TWO_PI_F * (f - rintf(f)), &zi[c], &zr[c]);
    }

    float acc0[4] = {0.f, 0.f, 0.f, 0.f};
    float acc1[4] = {0.f, 0.f, 0.f, 0.f};
#pragma unroll
    for (int j = 0; j < 28; ++j) {
#pragma unroll
        for (int c = 0; c < 4; ++c) {
            int m = 28 * c + j;
            float tt = fmaf(sA[m], zr[c], sB[m] * zi[c]);
            acc0[c] = fmaf(sV0[m], tt, acc0[c]);
            acc1[c] = fmaf(sV1[m], tt, acc1[c]);
            float nzr = fmaf(zr[c], cw_, -zi[c] * sw_);
            float nzi = fmaf(zi[c], cw_,  zr[c] * sw_);
            zr[c] = nzr; zi[c] = nzi;
        }
    }
    g_f[b][0][n] = (acc0[0] + acc0[1]) + (acc0[2] + acc0[3]);
    g_f[b][1][n] = (acc1[0] + acc1[1]) + (acc1[2] + acc1[3]);
}

// ---------------------------------------------------------------------------
// K3: resample field at particle positions. 15 taps, clamped (ref doesn't wrap).
// ---------------------------------------------------------------------------
__global__ __launch_bounds__(256) void k_resample(const float* __restrict__ x,
                                                  float* __restrict__ out)
{
    const int gid = blockIdx.x * 256 + threadIdx.x;   // 0..8191
    const int b   = gid >> 10;
    const float xv = x[gid];

    const double TWO_PI_D = 6.283185307179586476925286766559;
    const float  TAUF     = (float)(12.0 / ((TWO_PI_D * 2001.0) * (TWO_PI_D * 2001.0)));
    const float  inv4tau  = 1.f / (4.f * TAUF);
    const float C_HI = (float)(1.0 / 2001.0);
    const float C_LO = (float)(1.0 / 2001.0 - (double)((float)(1.0 / 2001.0)));

    const int m0 = __float2int_rn(xv * 2001.0f);
    float acc0 = 0.f, acc1 = 0.f;
#pragma unroll
    for (int j = -7; j <= 7; ++j) {
        int m = m0 + j;
        if (m < 0 || m > 2000) continue;
        float mf = (float)m;
        float hi = mf * C_HI;
        float X  = hi + (fmaf(mf, C_HI, -hi) + mf * C_LO);   // fp32(m/2001), ~1e-10
        float d  = xv - X;
        float wgt = __expf(-d * d * inv4tau);
        acc0 = fmaf(wgt, g_f[b][0][m], acc0);
        acc1 = fmaf(wgt, g_f[b][1][m], acc1);
    }
    const float invN = (float)(1.0 / 2001.0);
    out[2 * gid]     = acc0 * invN;
    out[2 * gid + 1] = acc1 * invN;
}

// ---------------------------------------------------------------------------
extern "C" void kernel_launch(void* const* d_in, const int* in_sizes, int n_in,
                              void* d_out, int out_size)
{
    (void)in_sizes; (void)n_in; (void)out_size;
    const float* x         = (const float*)d_in[0];
    const float* sigma_var = (const float*)d_in[1];
    const float* shift0    = (const float*)d_in[2];
    const float* shift1    = (const float*)d_in[3];
    const float* amp0      = (const float*)d_in[4];
    const float* amp1      = (const float*)d_in[5];
    float* out = (float*)d_out;

    k_modes   <<<dim3(NPG, NBATCH), 128>>>(x);
    k_field   <<<dim3(16,  NBATCH), 128>>>(sigma_var, shift0, shift1, amp0, amp1);
    k_resample<<<32, 256>>>(x, out);
}

// round 4
// speedup vs baseline: 1.4212x; 1.4212x over previous
#include <cuda_runtime.h>
#include <math.h>

// NUFFT layer, analytic band-limited reformulation (see round-1 header).
//  A_b[m] = sum_p cos(2*pi*m*x_p),  B_b[m] = sum_p sin(2*pi*m*x_p),  m = 0..111
//  field[b,c,n] = sum_m V_c[m] * (A_b[m] cos(2*pi*m*n/N) + B_b[m] sin(2*pi*m*n/N))
//  out[b,p,c]   = (1/N) * sum_{|j|<=7} exp(-(x_p - X_m)^2/(4 tau)) * field[b,c,m0+j]
//
// Round-3/4: k_modes uses register accumulators (32/thread) and a single
// 31-shfl recursive-halving cross-lane reduction instead of per-mode butterfly
// chains (round-2's latency disaster: 560 dependent shfls/thread, occ 6%).
// (Round-3 bench was an infra failure; this is the same design re-submitted.)

#define NMESHC 2001
#define NMODES 112          // modes >= 106 underflow to exactly 0 (as in reference fp32)
#define NBATCH 8
#define NPART  1024
#define NPGE   16           // effective partial groups (8 blocks x 2 halves)

__device__ float g_part[NBATCH][NPGE][2 * NMODES];  // partial A|B sums
__device__ float g_f[NBATCH][2][NMESHC];            // physical-space field

#define TWO_PI_F 6.2831853071795864769f

// frac(m*x) in ~[-0.5, 0.5]; exact split for m < 2^7, x fp32.
__device__ __forceinline__ float frac_mx(float m, float x)
{
    float hi = m * x;
    float lo = fmaf(m, x, -hi);           // exact residual (31-bit product)
    return (hi - rintf(hi)) + lo;         // hi - rintf(hi) exact
}

// ---------------------------------------------------------------------------
// K1: per-mode cos/sin particle sums.
// Block = (pg, b), 448 threads = 14 warps. Warp w: chunk c = w % 7 (16 modes),
// half h = w / 7. Lanes cover 64 particles (2 each). Inner loop: pure FMA.
// ---------------------------------------------------------------------------
__global__ __launch_bounds__(448) void k_modes(const float* __restrict__ x)
{
    const int pg   = blockIdx.x;
    const int b    = blockIdx.y;
    const int w    = threadIdx.x >> 5;
    const int lane = threadIdx.x & 31;
    const int c    = w % 7;
    const int h    = w / 7;

    const float* xb = x + b * NPART + pg * 128 + h * 64;

    float v[32];                          // v[2j]=Re(mode 16c+j), v[2j+1]=Im
#pragma unroll
    for (int k = 0; k < 32; ++k) v[k] = 0.f;

#pragma unroll
    for (int pp = 0; pp < 2; ++pp) {
        const float xv = xb[lane + 32 * pp];
        float sw_, cw_;                                   // step e^{2*pi*i*x}
        __sincosf(TWO_PI_F * (xv - rintf(xv)), &sw_, &cw_);
        float zr, zi;
        if (c == 0) { zr = 1.f; zi = 0.f; }
        else        { __sincosf(TWO_PI_F * frac_mx((float)(16 * c), xv), &zi, &zr); }
#pragma unroll
        for (int j = 0; j < 16; ++j) {
            v[2 * j]     += zr;
            v[2 * j + 1] += zi;
            float nzr = fmaf(zr, cw_, -zi * sw_);
            float nzi = fmaf(zi, cw_,  zr * sw_);
            zr = nzr; zi = nzi;
        }
    }

    // Distributed reduction: 32 values x 32 lanes -> lane l ends holding the
    // warp total of accumulator index bitrev5(l). 31 shfls total; the shfls
    // within each stage are independent (no dependent chains).
#pragma unroll
    for (int s = 0; s < 5; ++s) {
        const int half = 16 >> s;                      // live count / 2 this stage
        const bool up  = (lane >> s) & 1;
#pragma unroll
        for (int k = 0; k < half; ++k) {
            float send = up ? v[k] : v[k + half];
            float recv = __shfl_xor_sync(0xffffffffu, send, 1 << s);
            v[k] = (up ? v[k + half] : v[k]) + recv;
        }
    }

    const int r = __brev(lane) >> 27;     // original accumulator index
    const int m = 16 * c + (r >> 1);
    g_part[b][pg * 2 + h][(r & 1) * NMODES + m] = v[0];
}

// ---------------------------------------------------------------------------
// K2: field at all 2001 grid points, both channels.
// 4 independent 28-step rotation chains; (A,B,V0,V1) packed in float4 smem.
// ---------------------------------------------------------------------------
__global__ __launch_bounds__(128) void k_field(
    const float* __restrict__ sigma_var,
    const float* __restrict__ shift0,
    const float* __restrict__ shift1,
    const float* __restrict__ amp0,
    const float* __restrict__ amp1)
{
    const int b = blockIdx.y;
    const int t = threadIdx.x;
    const int n = blockIdx.x * 128 + t;

    __shared__ float4 s4[NMODES];

    const double TWO_PI_D = 6.283185307179586476925286766559;
    const double taud     = 12.0 / ((TWO_PI_D * 2001.0) * (TWO_PI_D * 2001.0));
    const float  TAUF     = (float)taud;
    const float  SQPIOTAU = (float)sqrt(3.14159265358979323846 / taud);

    const float s    = sigma_var[0];
    const float q0   = 25.f * shift0[0] * shift0[0];
    const float q1   = 25.f * shift1[0] * shift1[0];
    const float a0   = amp0[0];
    const float a1   = amp1[0];
    const float FOURPI = 12.566370614359172f;
    const float coef = TAUF - 0.5f * s * s;           // exp(K^2 tau - K^2 s^2/2)

    if (t < NMODES) {
        int m = t;
        float a = 0.f, bb = 0.f;
#pragma unroll
        for (int pg = 0; pg < NPGE; ++pg) {
            a  += g_part[b][pg][m];
            bb += g_part[b][pg][NMODES + m];
        }
        float kk = TWO_PI_F * (float)m;
        float K2 = kk * kk;
        float e  = SQPIOTAU * __expf(coef * K2);      // 0 for m >= 106 (as reference)
        float fold = (m == 0) ? 1.f : 2.f;
        float V0 = fold * (-a0) * FOURPI / (K2 + q0) * e;
        float inv = 1.f / (K2 + q1);
        float V1 = fold * a1 * FOURPI * inv * inv * e;
        s4[m] = make_float4(a, bb, V0, V1);
    }
    __syncthreads();
    if (n >= NMESHC) return;

    // phi = n/2001, Dekker-accurate
    const float C_HI = (float)(1.0 / 2001.0);
    const float C_LO = (float)(1.0 / 2001.0 - (double)((float)(1.0 / 2001.0)));
    const float nf     = (float)n;
    const float phi_hi = nf * C_HI;
    const float phi_lo = fmaf(nf, C_HI, -phi_hi) + nf * C_LO;

    float sw_, cw_;                                   // step e^{2*pi*i*phi}
    __sincosf(TWO_PI_F * ((phi_hi - rintf(phi_hi)) + phi_lo), &sw_, &cw_);

    float zr[4], zi[4];
    zr[0] = 1.f; zi[0] = 0.f;
#pragma unroll
    for (int c = 1; c < 4; ++c) {                     // base phase at m0 = 28c, exact
        float m0f = (float)(28 * c);
        float hi2 = m0f * phi_hi;
        float lo2 = fmaf(m0f, phi_hi, -hi2);
        float f   = (hi2 - rintf(hi2)) + (lo2 + m0f * phi_lo);
        __sincosf(TWO_PI_F * (f - rintf(f)), &zi[c], &zr[c]);
    }

    float acc0[4] = {0.f, 0.f, 0.f, 0.f};
    float acc1[4] = {0.f, 0.f, 0.f, 0.f};
#pragma unroll
    for (int j = 0; j < 28; ++j) {
#pragma unroll
        for (int c = 0; c < 4; ++c) {
            float4 q = s4[28 * c + j];
            float tt = fmaf(q.x, zr[c], q.y * zi[c]);
            acc0[c] = fmaf(q.z, tt, acc0[c]);
            acc1[c] = fmaf(q.w, tt, acc1[c]);
            float nzr = fmaf(zr[c], cw_, -zi[c] * sw_);
            float nzi = fmaf(zi[c], cw_,  zr[c] * sw_);
            zr[c] = nzr; zi[c] = nzi;
        }
    }
    g_f[b][0][n] = (acc0[0] + acc0[1]) + (acc0[2] + acc0[3]);
    g_f[b][1][n] = (acc1[0] + acc1[1]) + (acc1[2] + acc1[3]);
}

// ---------------------------------------------------------------------------
// K3: resample field at particle positions. 15 taps, clamped (ref doesn't wrap).
// ---------------------------------------------------------------------------
__global__ __launch_bounds__(256) void k_resample(const float* __restrict__ x,
                                                  float* __restrict__ out)
{
    const int gid = blockIdx.x * 256 + threadIdx.x;   // 0..8191
    const int b   = gid >> 10;
    const float xv = x[gid];

    const double TWO_PI_D = 6.283185307179586476925286766559;
    const float  TAUF     = (float)(12.0 / ((TWO_PI_D * 2001.0) * (TWO_PI_D * 2001.0)));
    const float  inv4tau  = 1.f / (4.f * TAUF);
    const float C_HI = (float)(1.0 / 2001.0);
    const float C_LO = (float)(1.0 / 2001.0 - (double)((float)(1.0 / 2001.0)));

    const int m0 = __float2int_rn(xv * 2001.0f);
    float acc0 = 0.f, acc1 = 0.f;
#pragma unroll
    for (int j = -7; j <= 7; ++j) {
        int m = m0 + j;
        if (m < 0 || m > 2000) continue;
        float mf = (float)m;
        float hi = mf * C_HI;
        float X  = hi + (fmaf(mf, C_HI, -hi) + mf * C_LO);   // fp32(m/2001)
        float d  = xv - X;
        float wgt = __expf(-d * d * inv4tau);
        acc0 = fmaf(wgt, g_f[b][0][m], acc0);
        acc1 = fmaf(wgt, g_f[b][1][m], acc1);
    }
    const float invN = (float)(1.0 / 2001.0);
    out[2 * gid]     = acc0 * invN;
    out[2 * gid + 1] = acc1 * invN;
}

// ---------------------------------------------------------------------------
extern "C" void kernel_launch(void* const* d_in, const int* in_sizes, int n_in,
                              void* d_out, int out_size)
{
    (void)in_sizes; (void)n_in; (void)out_size;
    const float* x         = (const float*)d_in[0];
    const float* sigma_var = (const float*)d_in[1];
    const float* shift0    = (const float*)d_in[2];
    const float* shift1    = (const float*)d_in[3];
    const float* amp0      = (const float*)d_in[4];
    const float* amp1      = (const float*)d_in[5];
    float* out = (float*)d_out;

    k_modes   <<<dim3(8,  NBATCH), 448>>>(x);
    k_field   <<<dim3(16, NBATCH), 128>>>(sigma_var, shift0, shift1, amp0, amp1);
    k_resample<<<32, 256>>>(x, out);
}